// round 4
// baseline (speedup 1.0000x reference)
#include <cuda_runtime.h>

// Gibbs sweep over DIM=32 coordinates of B rows.
// x_i <- base_i + sum_j A_ij x_j,   A_ij = -P_ij/P_ii (diag 0),
// base_i = mu_i + sqrt(1/P_ii)*n_i.
//
// R3: A matrix is precomputed by a prep kernel into a __device__ global and
// read in the sweep via UNIFORM LDG.128 (1 L1 wavefront/instr) instead of
// LDS broadcasts (4 crossbar cyc/instr) -- removes the 4GB smem delivery
// that bound R2. Two rows per thread halves warp count (halves A-LDG issue).

#define DIM 32
#define THREADS 128
#define ROWS_PER_THREAD 2
#define ROWS_PER_BLOCK (THREADS * ROWS_PER_THREAD)   // 256

__device__ float g_A[DIM * DIM];   // A_ij = -P_ij / P_ii, diag 0

__global__ void prep_kernel(const float* __restrict__ P)
{
    int e = threadIdx.x;                 // 1024 threads
    int r = e >> 5, c = e & 31;
    float pii = P[r * DIM + r];
    float v = -P[e] / pii;
    g_A[e] = (r == c) ? 0.0f : v;
}

__device__ __forceinline__ unsigned long long f2u(float2 v) {
    unsigned long long u; __builtin_memcpy(&u, &v, 8); return u;
}
__device__ __forceinline__ float2 u2f(unsigned long long u) {
    float2 v; __builtin_memcpy(&v, &u, 8); return v;
}
__device__ __forceinline__ float2 ffma2(float2 a, float2 b, float2 c) {
    unsigned long long d;
    asm("fma.rn.f32x2 %0, %1, %2, %3;"
        : "=l"(d) : "l"(f2u(a)), "l"(f2u(b)), "l"(f2u(c)));
    return u2f(d);
}
__device__ __forceinline__ float2 fadd2(float2 a, float2 b) {
    unsigned long long d;
    asm("add.rn.f32x2 %0, %1, %2;"
        : "=l"(d) : "l"(f2u(a)), "l"(f2u(b)));
    return u2f(d);
}

__global__ __launch_bounds__(THREADS, 4)
void gibbs_sweep_kernel(const float* __restrict__ x,
                        const float* __restrict__ noise,
                        const float* __restrict__ P,
                        const float* __restrict__ mu,
                        float* __restrict__ out,
                        int B)
{
    __shared__ float sgf[DIM];                 // sigma_i = sqrt(1/P_ii)
    __shared__ float muf[DIM];
    // One buffer, reused:
    //  (a) x transpose-stage : float4[256*8], XOR-swizzled  (32 KB)
    //  (b) base = mu+sig*n   : float [256*33], pad-33       (33.8 KB)
    //  (c) out transpose-stage (same layout as (a))
    __shared__ __align__(16) float buf[ROWS_PER_BLOCK * 33];

    const int tid = threadIdx.x;

    if (tid < DIM) {
        float pii = P[tid * DIM + tid];
        sgf[tid] = sqrtf(1.0f / pii);
        muf[tid] = mu[tid];
    }
    __syncthreads();

    const int R0 = blockIdx.x * ROWS_PER_BLOCK;
    float4* st4 = (float4*)buf;

    // ---- stage x: coalesced LDG.128 -> swizzled SMEM ----
    const float4* gx = (const float4*)x;
    #pragma unroll
    for (int k = 0; k < 16; ++k) {
        int idx = k * THREADS + tid;           // 0..2047, coalesced
        int row = idx >> 3;
        int c   = idx & 7;
        int gr  = R0 + row;
        float4 v = (gr < B) ? gx[(size_t)gr * 8 + c]
                            : make_float4(0.f, 0.f, 0.f, 0.f);
        st4[row * 8 + (c ^ ((row >> 2) & 7))] = v;
    }
    __syncthreads();

    // ---- gather my two rows into registers (swizzled LDS.128) ----
    const int sw = (tid >> 2) & 7;
    float2 sA[16], sB[16];
    #pragma unroll
    for (int c = 0; c < 8; ++c) {
        float4 v = st4[tid * 8 + (c ^ sw)];
        sA[2 * c]     = make_float2(v.x, v.y);
        sA[2 * c + 1] = make_float2(v.z, v.w);
        float4 w = st4[(tid + THREADS) * 8 + (c ^ sw)];
        sB[2 * c]     = make_float2(w.x, w.y);
        sB[2 * c + 1] = make_float2(w.z, w.w);
    }
    __syncthreads();

    // ---- stage base = mu + sigma*noise into pad-33 layout (reuses buf) ----
    const float4* gn = (const float4*)noise;
    #pragma unroll
    for (int k = 0; k < 16; ++k) {
        int idx = k * THREADS + tid;
        int row = idx >> 3;
        int c   = idx & 7;
        int gr  = R0 + row;
        float4 n4 = (gr < B) ? gn[(size_t)gr * 8 + c]
                             : make_float4(0.f, 0.f, 0.f, 0.f);
        float* d = buf + row * 33 + c * 4;
        d[0] = fmaf(sgf[c * 4 + 0], n4.x, muf[c * 4 + 0]);
        d[1] = fmaf(sgf[c * 4 + 1], n4.y, muf[c * 4 + 1]);
        d[2] = fmaf(sgf[c * 4 + 2], n4.z, muf[c * 4 + 2]);
        d[3] = fmaf(sgf[c * 4 + 3], n4.w, muf[c * 4 + 3]);
    }
    __syncthreads();

    const float* pbA = buf + tid * 33;                  // base rows (pad-33)
    const float* pbB = buf + (tid + THREADS) * 33;
    const float4* gA4 = (const float4*)g_A;

    // ---- the sequential sweep; A via uniform LDG.128 (L1-hit) ----
    #pragma unroll
    for (int i = 0; i < DIM; ++i) {
        float2 a0 = make_float2(0.f, 0.f), a1 = make_float2(0.f, 0.f);
        float2 b0 = make_float2(0.f, 0.f), b1 = make_float2(0.f, 0.f);
        #pragma unroll
        for (int t = 0; t < 8; ++t) {
            float4 p = __ldg(&gA4[i * 8 + t]);   // uniform across warp
            float2 p0 = make_float2(p.x, p.y);
            float2 p1 = make_float2(p.z, p.w);
            a0 = ffma2(sA[2 * t],     p0, a0);
            a1 = ffma2(sA[2 * t + 1], p1, a1);
            b0 = ffma2(sB[2 * t],     p0, b0);
            b1 = ffma2(sB[2 * t + 1], p1, b1);
        }
        float2 ra = fadd2(a0, a1);
        float2 rb = fadd2(b0, b1);
        float nA = (ra.x + ra.y) + pbA[i];
        float nB = (rb.x + rb.y) + pbB[i];
        if (i & 1) { sA[i >> 1].y = nA; sB[i >> 1].y = nB; }
        else       { sA[i >> 1].x = nA; sB[i >> 1].x = nB; }
    }

    __syncthreads();   // all lanes done with base region before clobbering
    // ---- scatter rows back to swizzled SMEM, then coalesced STG.128 ----
    #pragma unroll
    for (int c = 0; c < 8; ++c) {
        st4[tid * 8 + (c ^ sw)] =
            make_float4(sA[2 * c].x, sA[2 * c].y, sA[2 * c + 1].x, sA[2 * c + 1].y);
        st4[(tid + THREADS) * 8 + (c ^ sw)] =
            make_float4(sB[2 * c].x, sB[2 * c].y, sB[2 * c + 1].x, sB[2 * c + 1].y);
    }
    __syncthreads();
    float4* gout = (float4*)out;
    #pragma unroll
    for (int k = 0; k < 16; ++k) {
        int idx = k * THREADS + tid;
        int row = idx >> 3;
        int c   = idx & 7;
        int gr  = R0 + row;
        if (gr < B) gout[(size_t)gr * 8 + c] = st4[row * 8 + (c ^ ((row >> 2) & 7))];
    }
}

extern "C" void kernel_launch(void* const* d_in, const int* in_sizes, int n_in,
                              void* d_out, int out_size)
{
    const float* x     = (const float*)d_in[0];
    const float* noise = (const float*)d_in[1];
    const float* P     = (const float*)d_in[2];
    const float* mu    = (const float*)d_in[3];
    float* out = (float*)d_out;

    int B = in_sizes[0] / DIM;

    prep_kernel<<<1, DIM * DIM>>>(P);

    int grid = (B + ROWS_PER_BLOCK - 1) / ROWS_PER_BLOCK;
    gibbs_sweep_kernel<<<grid, THREADS>>>(x, noise, P, mu, out, B);
}

// round 6
// speedup vs baseline: 6.0495x; 6.0495x over previous
#include <cuda_runtime.h>

// Gibbs sweep over DIM=32 coordinates of B rows.
// x_i <- base_i + sum_j A_ij x_j,   A_ij = -P_ij/P_ii (diag 0),
// base_i = mu_i + sqrt(1/P_ii)*n_i.
//
// R5 = R3 (1 row/thread, 96 regs, no spill) with ONE change: A is fetched via
// uniform LDG.128 from a precomputed __device__ global instead of smem
// broadcast LDS (which delivered 4GB over the crossbar and bound R3 at L1=90%).

#define DIM 32
#define THREADS 128
#define ROWS_PER_BLOCK 128

__device__ float g_A[DIM * DIM];   // A_ij = -P_ij / P_ii, diag 0

__global__ void prep_kernel(const float* __restrict__ P)
{
    int e = threadIdx.x;                 // 1024 threads
    int r = e >> 5, c = e & 31;
    float pii = P[r * DIM + r];
    float v = -P[e] / pii;
    g_A[e] = (r == c) ? 0.0f : v;
}

__device__ __forceinline__ unsigned long long f2u(float2 v) {
    unsigned long long u; __builtin_memcpy(&u, &v, 8); return u;
}
__device__ __forceinline__ float2 u2f(unsigned long long u) {
    float2 v; __builtin_memcpy(&v, &u, 8); return v;
}
__device__ __forceinline__ float2 ffma2(float2 a, float2 b, float2 c) {
    unsigned long long d;
    asm("fma.rn.f32x2 %0, %1, %2, %3;"
        : "=l"(d) : "l"(f2u(a)), "l"(f2u(b)), "l"(f2u(c)));
    return u2f(d);
}
__device__ __forceinline__ float2 fadd2(float2 a, float2 b) {
    unsigned long long d;
    asm("add.rn.f32x2 %0, %1, %2;"
        : "=l"(d) : "l"(f2u(a)), "l"(f2u(b)));
    return u2f(d);
}

__global__ __launch_bounds__(THREADS, 5)
void gibbs_sweep_kernel(const float* __restrict__ x,
                        const float* __restrict__ noise,
                        const float* __restrict__ P,
                        const float* __restrict__ mu,
                        float* __restrict__ out,
                        int B)
{
    __shared__ float sgf[DIM];                 // sigma_i = sqrt(1/P_ii)
    __shared__ float muf[DIM];
    // One buffer, reused:
    //  (a) x transpose-stage : float4[128*8], XOR-swizzled  (16 KB)
    //  (b) base = mu+sig*n   : float [128*33], pad-33       (16.9 KB)
    //  (c) out transpose-stage (same layout as (a))
    __shared__ __align__(16) float buf[ROWS_PER_BLOCK * 33];

    const int tid = threadIdx.x;

    if (tid < DIM) {
        float pii = P[tid * DIM + tid];
        sgf[tid] = sqrtf(1.0f / pii);
        muf[tid] = mu[tid];
    }
    __syncthreads();

    const int R0 = blockIdx.x * ROWS_PER_BLOCK;
    float4* st4 = (float4*)buf;

    // ---- stage x: coalesced LDG.128 -> swizzled SMEM ----
    const float4* gx = (const float4*)x;
    #pragma unroll
    for (int k = 0; k < 8; ++k) {
        int idx = k * THREADS + tid;           // 0..1023 linear, coalesced
        int row = idx >> 3;
        int c   = idx & 7;
        int gr  = R0 + row;
        float4 v = (gr < B) ? gx[(size_t)gr * 8 + c]
                            : make_float4(0.f, 0.f, 0.f, 0.f);
        st4[row * 8 + (c ^ ((row >> 2) & 7))] = v;
    }
    __syncthreads();

    // ---- gather my row into registers (conflict-free swizzled LDS.128) ----
    const int sw = (tid >> 2) & 7;
    float2 s[16];
    #pragma unroll
    for (int c = 0; c < 8; ++c) {
        float4 v = st4[tid * 8 + (c ^ sw)];
        s[2 * c]     = make_float2(v.x, v.y);
        s[2 * c + 1] = make_float2(v.z, v.w);
    }
    __syncthreads();

    // ---- stage base = mu + sigma*noise into pad-33 layout (reuses buf) ----
    const float4* gn = (const float4*)noise;
    #pragma unroll
    for (int k = 0; k < 8; ++k) {
        int idx = k * THREADS + tid;
        int row = idx >> 3;
        int c   = idx & 7;
        int gr  = R0 + row;
        float4 n4 = (gr < B) ? gn[(size_t)gr * 8 + c]
                             : make_float4(0.f, 0.f, 0.f, 0.f);
        float* d = buf + row * 33 + c * 4;
        d[0] = fmaf(sgf[c * 4 + 0], n4.x, muf[c * 4 + 0]);
        d[1] = fmaf(sgf[c * 4 + 1], n4.y, muf[c * 4 + 1]);
        d[2] = fmaf(sgf[c * 4 + 2], n4.z, muf[c * 4 + 2]);
        d[3] = fmaf(sgf[c * 4 + 3], n4.w, muf[c * 4 + 3]);
    }
    __syncthreads();

    const float* pb = buf + tid * 33;          // my base row (pad-33, conflict-free)
    const float4* gA4 = (const float4*)g_A;

    // ---- the sequential sweep; A via uniform LDG.128 (L1-resident 4KB) ----
    #pragma unroll
    for (int i = 0; i < DIM; ++i) {
        float2 a0 = make_float2(0.f, 0.f), a1 = make_float2(0.f, 0.f);
        float2 a2 = make_float2(0.f, 0.f), a3 = make_float2(0.f, 0.f);
        #pragma unroll
        for (int t = 0; t < 4; ++t) {
            float4 p = __ldg(&gA4[i * 8 + 2 * t]);       // uniform across warp
            float4 q = __ldg(&gA4[i * 8 + 2 * t + 1]);
            a0 = ffma2(s[4 * t],     make_float2(p.x, p.y), a0);
            a1 = ffma2(s[4 * t + 1], make_float2(p.z, p.w), a1);
            a2 = ffma2(s[4 * t + 2], make_float2(q.x, q.y), a2);
            a3 = ffma2(s[4 * t + 3], make_float2(q.z, q.w), a3);
        }
        float2 sa = fadd2(fadd2(a0, a1), fadd2(a2, a3));
        float nv = (sa.x + sa.y) + pb[i];
        if (i & 1) s[i >> 1].y = nv;
        else       s[i >> 1].x = nv;
    }

    __syncthreads();   // sweep done everywhere before clobbering base region
    // ---- scatter row back to swizzled SMEM, then coalesced STG.128 ----
    #pragma unroll
    for (int c = 0; c < 8; ++c) {
        st4[tid * 8 + (c ^ sw)] =
            make_float4(s[2 * c].x, s[2 * c].y, s[2 * c + 1].x, s[2 * c + 1].y);
    }
    __syncthreads();
    float4* gout = (float4*)out;
    #pragma unroll
    for (int k = 0; k < 8; ++k) {
        int idx = k * THREADS + tid;
        int row = idx >> 3;
        int c   = idx & 7;
        int gr  = R0 + row;
        if (gr < B) gout[(size_t)gr * 8 + c] = st4[row * 8 + (c ^ ((row >> 2) & 7))];
    }
}

extern "C" void kernel_launch(void* const* d_in, const int* in_sizes, int n_in,
                              void* d_out, int out_size)
{
    const float* x     = (const float*)d_in[0];
    const float* noise = (const float*)d_in[1];
    const float* P     = (const float*)d_in[2];
    const float* mu    = (const float*)d_in[3];
    float* out = (float*)d_out;

    int B = in_sizes[0] / DIM;

    prep_kernel<<<1, DIM * DIM>>>(P);

    int grid = (B + ROWS_PER_BLOCK - 1) / ROWS_PER_BLOCK;
    gibbs_sweep_kernel<<<grid, THREADS>>>(x, noise, P, mu, out, B);
}

// round 7
// speedup vs baseline: 12.6216x; 2.0864x over previous
#include <cuda_runtime.h>

// Gibbs sweep over DIM=32 coordinates of B rows.
// x_i <- base_i + sum_j A_ij x_j,   A_ij = -P_ij/P_ii (diag 0),
// base_i = mu_i + sqrt(1/P_ii)*n_i.
//
// R6 = R3 (1 row/thread, 96 regs) with ONE change: the A matrix is read from
// __constant__ memory (LDCU uniform-const port, floor 1 cyc, OFF the MIO/L1
// pipe) instead of smem-broadcast LDS (R3, crossbar-bound at 4 cyc/instr)
// or uniform LDG (R5, even costlier through L1tex).

#define DIM 32
#define THREADS 128
#define ROWS_PER_BLOCK 128

__device__   float  g_A[DIM * DIM];     // staging for prep kernel output
__constant__ float2 c_A2[DIM * DIM / 2]; // A as float2 pairs, row-major

__global__ void prep_kernel(const float* __restrict__ P)
{
    int e = threadIdx.x;                 // 1024 threads
    int r = e >> 5, c = e & 31;
    float pii = P[r * DIM + r];
    float v = -P[e] / pii;
    g_A[e] = (r == c) ? 0.0f : v;
}

__device__ __forceinline__ unsigned long long f2u(float2 v) {
    unsigned long long u; __builtin_memcpy(&u, &v, 8); return u;
}
__device__ __forceinline__ float2 u2f(unsigned long long u) {
    float2 v; __builtin_memcpy(&v, &u, 8); return v;
}
__device__ __forceinline__ float2 ffma2(float2 a, float2 b, float2 c) {
    unsigned long long d;
    asm("fma.rn.f32x2 %0, %1, %2, %3;"
        : "=l"(d) : "l"(f2u(a)), "l"(f2u(b)), "l"(f2u(c)));
    return u2f(d);
}
__device__ __forceinline__ float2 fadd2(float2 a, float2 b) {
    unsigned long long d;
    asm("add.rn.f32x2 %0, %1, %2;"
        : "=l"(d) : "l"(f2u(a)), "l"(f2u(b)));
    return u2f(d);
}

__global__ __launch_bounds__(THREADS, 5)
void gibbs_sweep_kernel(const float* __restrict__ x,
                        const float* __restrict__ noise,
                        const float* __restrict__ P,
                        const float* __restrict__ mu,
                        float* __restrict__ out,
                        int B)
{
    __shared__ float sgf[DIM];                 // sigma_i = sqrt(1/P_ii)
    __shared__ float muf[DIM];
    // One buffer, reused:
    //  (a) x transpose-stage : float4[128*8], XOR-swizzled  (16 KB)
    //  (b) base = mu+sig*n   : float [128*33], pad-33       (16.9 KB)
    //  (c) out transpose-stage (same layout as (a))
    __shared__ __align__(16) float buf[ROWS_PER_BLOCK * 33];

    const int tid = threadIdx.x;

    if (tid < DIM) {
        float pii = P[tid * DIM + tid];
        sgf[tid] = sqrtf(1.0f / pii);
        muf[tid] = mu[tid];
    }
    __syncthreads();

    const int R0 = blockIdx.x * ROWS_PER_BLOCK;
    float4* st4 = (float4*)buf;

    // ---- stage x: coalesced LDG.128 -> swizzled SMEM ----
    const float4* gx = (const float4*)x;
    #pragma unroll
    for (int k = 0; k < 8; ++k) {
        int idx = k * THREADS + tid;           // 0..1023 linear, coalesced
        int row = idx >> 3;
        int c   = idx & 7;
        int gr  = R0 + row;
        float4 v = (gr < B) ? gx[(size_t)gr * 8 + c]
                            : make_float4(0.f, 0.f, 0.f, 0.f);
        st4[row * 8 + (c ^ ((row >> 2) & 7))] = v;
    }
    __syncthreads();

    // ---- gather my row into registers (conflict-free swizzled LDS.128) ----
    const int sw = (tid >> 2) & 7;
    float2 s[16];
    #pragma unroll
    for (int c = 0; c < 8; ++c) {
        float4 v = st4[tid * 8 + (c ^ sw)];
        s[2 * c]     = make_float2(v.x, v.y);
        s[2 * c + 1] = make_float2(v.z, v.w);
    }
    __syncthreads();

    // ---- stage base = mu + sigma*noise into pad-33 layout (reuses buf) ----
    const float4* gn = (const float4*)noise;
    #pragma unroll
    for (int k = 0; k < 8; ++k) {
        int idx = k * THREADS + tid;
        int row = idx >> 3;
        int c   = idx & 7;
        int gr  = R0 + row;
        float4 n4 = (gr < B) ? gn[(size_t)gr * 8 + c]
                             : make_float4(0.f, 0.f, 0.f, 0.f);
        float* d = buf + row * 33 + c * 4;
        d[0] = fmaf(sgf[c * 4 + 0], n4.x, muf[c * 4 + 0]);
        d[1] = fmaf(sgf[c * 4 + 1], n4.y, muf[c * 4 + 1]);
        d[2] = fmaf(sgf[c * 4 + 2], n4.z, muf[c * 4 + 2]);
        d[3] = fmaf(sgf[c * 4 + 3], n4.w, muf[c * 4 + 3]);
    }
    __syncthreads();

    const float* pb = buf + tid * 33;          // my base row (pad-33, conflict-free)

    // ---- the sequential sweep; A via __constant__ (LDCU, uniform port) ----
    #pragma unroll
    for (int i = 0; i < DIM; ++i) {
        float2 a0 = make_float2(0.f, 0.f), a1 = make_float2(0.f, 0.f);
        float2 a2 = make_float2(0.f, 0.f), a3 = make_float2(0.f, 0.f);
        #pragma unroll
        for (int t = 0; t < 4; ++t) {
            // compile-time constant offsets -> ld.const -> LDCU (uniform path)
            a0 = ffma2(s[4 * t],     c_A2[i * 16 + 4 * t + 0], a0);
            a1 = ffma2(s[4 * t + 1], c_A2[i * 16 + 4 * t + 1], a1);
            a2 = ffma2(s[4 * t + 2], c_A2[i * 16 + 4 * t + 2], a2);
            a3 = ffma2(s[4 * t + 3], c_A2[i * 16 + 4 * t + 3], a3);
        }
        float2 sa = fadd2(fadd2(a0, a1), fadd2(a2, a3));
        float nv = (sa.x + sa.y) + pb[i];
        if (i & 1) s[i >> 1].y = nv;
        else       s[i >> 1].x = nv;
    }

    __syncthreads();   // sweep done everywhere before clobbering base region
    // ---- scatter row back to swizzled SMEM, then coalesced STG.128 ----
    #pragma unroll
    for (int c = 0; c < 8; ++c) {
        st4[tid * 8 + (c ^ sw)] =
            make_float4(s[2 * c].x, s[2 * c].y, s[2 * c + 1].x, s[2 * c + 1].y);
    }
    __syncthreads();
    float4* gout = (float4*)out;
    #pragma unroll
    for (int k = 0; k < 8; ++k) {
        int idx = k * THREADS + tid;
        int row = idx >> 3;
        int c   = idx & 7;
        int gr  = R0 + row;
        if (gr < B) gout[(size_t)gr * 8 + c] = st4[row * 8 + (c ^ ((row >> 2) & 7))];
    }
}

extern "C" void kernel_launch(void* const* d_in, const int* in_sizes, int n_in,
                              void* d_out, int out_size)
{
    const float* x     = (const float*)d_in[0];
    const float* noise = (const float*)d_in[1];
    const float* P     = (const float*)d_in[2];
    const float* mu    = (const float*)d_in[3];
    float* out = (float*)d_out;

    int B = in_sizes[0] / DIM;

    // 1) compute A into g_A on device
    prep_kernel<<<1, DIM * DIM>>>(P);

    // 2) D2D copy g_A -> __constant__ c_A2 (graph-capturable memcpy node)
    void* gA_addr = nullptr;
    cudaGetSymbolAddress(&gA_addr, g_A);
    cudaMemcpyToSymbolAsync(c_A2, gA_addr, sizeof(float) * DIM * DIM, 0,
                            cudaMemcpyDeviceToDevice, 0);

    // 3) the sweep
    int grid = (B + ROWS_PER_BLOCK - 1) / ROWS_PER_BLOCK;
    gibbs_sweep_kernel<<<grid, THREADS>>>(x, noise, P, mu, out, B);
}

// round 8
// speedup vs baseline: 12.8648x; 1.0193x over previous
#include <cuda_runtime.h>

// Gibbs sweep over DIM=32 coordinates of B rows.
// x_i <- base_i + sum_j A_ij x_j,   A_ij = -P_ij/P_ii (diag 0),
// base_i = mu_i + sqrt(1/P_ii)*n_i.
//
// R7 = R6 (constant-memory A via LDCU, 1 row/thread, 96 regs) with issue-slot
// trims: A fetched as float4 (LDCU.128, halves const-load count) and the base
// term folded into accumulator init (drops 32 scalar adds).

#define DIM 32
#define THREADS 128
#define ROWS_PER_BLOCK 128

__device__   float  g_A[DIM * DIM];      // staging for prep kernel output
__constant__ float4 c_A4[DIM * 8];       // A row-major as float4s

__global__ void prep_kernel(const float* __restrict__ P)
{
    int e = threadIdx.x;                 // 1024 threads
    int r = e >> 5, c = e & 31;
    float pii = P[r * DIM + r];
    float v = -P[e] / pii;
    g_A[e] = (r == c) ? 0.0f : v;
}

__device__ __forceinline__ unsigned long long f2u(float2 v) {
    unsigned long long u; __builtin_memcpy(&u, &v, 8); return u;
}
__device__ __forceinline__ float2 u2f(unsigned long long u) {
    float2 v; __builtin_memcpy(&v, &u, 8); return v;
}
__device__ __forceinline__ float2 ffma2(float2 a, float2 b, float2 c) {
    unsigned long long d;
    asm("fma.rn.f32x2 %0, %1, %2, %3;"
        : "=l"(d) : "l"(f2u(a)), "l"(f2u(b)), "l"(f2u(c)));
    return u2f(d);
}
__device__ __forceinline__ float2 fadd2(float2 a, float2 b) {
    unsigned long long d;
    asm("add.rn.f32x2 %0, %1, %2;"
        : "=l"(d) : "l"(f2u(a)), "l"(f2u(b)));
    return u2f(d);
}

__global__ __launch_bounds__(THREADS, 5)
void gibbs_sweep_kernel(const float* __restrict__ x,
                        const float* __restrict__ noise,
                        const float* __restrict__ P,
                        const float* __restrict__ mu,
                        float* __restrict__ out,
                        int B)
{
    __shared__ float sgf[DIM];                 // sigma_i = sqrt(1/P_ii)
    __shared__ float muf[DIM];
    // One buffer, reused:
    //  (a) x transpose-stage : float4[128*8], XOR-swizzled  (16 KB)
    //  (b) base = mu+sig*n   : float [128*33], pad-33       (16.9 KB)
    //  (c) out transpose-stage (same layout as (a))
    __shared__ __align__(16) float buf[ROWS_PER_BLOCK * 33];

    const int tid = threadIdx.x;

    if (tid < DIM) {
        float pii = P[tid * DIM + tid];
        sgf[tid] = sqrtf(1.0f / pii);
        muf[tid] = mu[tid];
    }
    __syncthreads();

    const int R0 = blockIdx.x * ROWS_PER_BLOCK;
    float4* st4 = (float4*)buf;

    // ---- stage x: coalesced LDG.128 -> swizzled SMEM ----
    const float4* gx = (const float4*)x;
    #pragma unroll
    for (int k = 0; k < 8; ++k) {
        int idx = k * THREADS + tid;           // 0..1023 linear, coalesced
        int row = idx >> 3;
        int c   = idx & 7;
        int gr  = R0 + row;
        float4 v = (gr < B) ? gx[(size_t)gr * 8 + c]
                            : make_float4(0.f, 0.f, 0.f, 0.f);
        st4[row * 8 + (c ^ ((row >> 2) & 7))] = v;
    }
    __syncthreads();

    // ---- gather my row into registers (conflict-free swizzled LDS.128) ----
    const int sw = (tid >> 2) & 7;
    float2 s[16];
    #pragma unroll
    for (int c = 0; c < 8; ++c) {
        float4 v = st4[tid * 8 + (c ^ sw)];
        s[2 * c]     = make_float2(v.x, v.y);
        s[2 * c + 1] = make_float2(v.z, v.w);
    }
    __syncthreads();

    // ---- stage base = mu + sigma*noise into pad-33 layout (reuses buf) ----
    const float4* gn = (const float4*)noise;
    #pragma unroll
    for (int k = 0; k < 8; ++k) {
        int idx = k * THREADS + tid;
        int row = idx >> 3;
        int c   = idx & 7;
        int gr  = R0 + row;
        float4 n4 = (gr < B) ? gn[(size_t)gr * 8 + c]
                             : make_float4(0.f, 0.f, 0.f, 0.f);
        float* d = buf + row * 33 + c * 4;
        d[0] = fmaf(sgf[c * 4 + 0], n4.x, muf[c * 4 + 0]);
        d[1] = fmaf(sgf[c * 4 + 1], n4.y, muf[c * 4 + 1]);
        d[2] = fmaf(sgf[c * 4 + 2], n4.z, muf[c * 4 + 2]);
        d[3] = fmaf(sgf[c * 4 + 3], n4.w, muf[c * 4 + 3]);
    }
    __syncthreads();

    const float* pb = buf + tid * 33;          // my base row (pad-33, conflict-free)

    // ---- the sequential sweep; A via LDCU.128 (constant port) ----
    #pragma unroll
    for (int i = 0; i < DIM; ++i) {
        // base term folded into a0's init
        float2 a0 = make_float2(pb[i], 0.f);
        float2 a1 = make_float2(0.f, 0.f);
        float2 a2 = make_float2(0.f, 0.f);
        float2 a3 = make_float2(0.f, 0.f);
        // accum j consumes float4s {2j, 2j+1} -> s[4j..4j+3]
        {
            float4 q = c_A4[i * 8 + 0];
            a0 = ffma2(s[0], make_float2(q.x, q.y), a0);
            a0 = ffma2(s[1], make_float2(q.z, q.w), a0);
            float4 r = c_A4[i * 8 + 1];
            a0 = ffma2(s[2], make_float2(r.x, r.y), a0);
            a0 = ffma2(s[3], make_float2(r.z, r.w), a0);
        }
        {
            float4 q = c_A4[i * 8 + 2];
            a1 = ffma2(s[4], make_float2(q.x, q.y), a1);
            a1 = ffma2(s[5], make_float2(q.z, q.w), a1);
            float4 r = c_A4[i * 8 + 3];
            a1 = ffma2(s[6], make_float2(r.x, r.y), a1);
            a1 = ffma2(s[7], make_float2(r.z, r.w), a1);
        }
        {
            float4 q = c_A4[i * 8 + 4];
            a2 = ffma2(s[8],  make_float2(q.x, q.y), a2);
            a2 = ffma2(s[9],  make_float2(q.z, q.w), a2);
            float4 r = c_A4[i * 8 + 5];
            a2 = ffma2(s[10], make_float2(r.x, r.y), a2);
            a2 = ffma2(s[11], make_float2(r.z, r.w), a2);
        }
        {
            float4 q = c_A4[i * 8 + 6];
            a3 = ffma2(s[12], make_float2(q.x, q.y), a3);
            a3 = ffma2(s[13], make_float2(q.z, q.w), a3);
            float4 r = c_A4[i * 8 + 7];
            a3 = ffma2(s[14], make_float2(r.x, r.y), a3);
            a3 = ffma2(s[15], make_float2(r.z, r.w), a3);
        }
        float2 sa = fadd2(fadd2(a0, a1), fadd2(a2, a3));
        float nv = sa.x + sa.y;
        if (i & 1) s[i >> 1].y = nv;
        else       s[i >> 1].x = nv;
    }

    __syncthreads();   // sweep done everywhere before clobbering base region
    // ---- scatter row back to swizzled SMEM, then coalesced STG.128 ----
    #pragma unroll
    for (int c = 0; c < 8; ++c) {
        st4[tid * 8 + (c ^ sw)] =
            make_float4(s[2 * c].x, s[2 * c].y, s[2 * c + 1].x, s[2 * c + 1].y);
    }
    __syncthreads();
    float4* gout = (float4*)out;
    #pragma unroll
    for (int k = 0; k < 8; ++k) {
        int idx = k * THREADS + tid;
        int row = idx >> 3;
        int c   = idx & 7;
        int gr  = R0 + row;
        if (gr < B) gout[(size_t)gr * 8 + c] = st4[row * 8 + (c ^ ((row >> 2) & 7))];
    }
}

extern "C" void kernel_launch(void* const* d_in, const int* in_sizes, int n_in,
                              void* d_out, int out_size)
{
    const float* x     = (const float*)d_in[0];
    const float* noise = (const float*)d_in[1];
    const float* P     = (const float*)d_in[2];
    const float* mu    = (const float*)d_in[3];
    float* out = (float*)d_out;

    int B = in_sizes[0] / DIM;

    // 1) compute A into g_A on device
    prep_kernel<<<1, DIM * DIM>>>(P);

    // 2) D2D copy g_A -> __constant__ c_A4 (graph-capturable memcpy node)
    void* gA_addr = nullptr;
    cudaGetSymbolAddress(&gA_addr, g_A);
    cudaMemcpyToSymbolAsync(c_A4, gA_addr, sizeof(float) * DIM * DIM, 0,
                            cudaMemcpyDeviceToDevice, 0);

    // 3) the sweep
    int grid = (B + ROWS_PER_BLOCK - 1) / ROWS_PER_BLOCK;
    gibbs_sweep_kernel<<<grid, THREADS>>>(x, noise, P, mu, out, B);
}

// round 11
// speedup vs baseline: 14.0098x; 1.0890x over previous
#include <cuda_runtime.h>

// Gibbs sweep over DIM=32 coordinates of B rows.
// x_new_i = base_i + sum_{j<i} A_ij x_new_j + sum_{j>i} A_ij x_old_j,
// A_ij = -P_ij/P_ii (diag 0), base_i = mu_i + sqrt(1/P_ii)*n_i.
//
// R8: triangular column-order reformulation.
//   Phase 1: r = base + U x_old   (x_old scalars streamed from smem)
//   Phase 2: forward substitution, column-order -> no horizontal reductions.
// Register state = r only (32 floats) -> 8 blocks/SM (occ 50%).
// A columns (upper/lower masked, zero-padded) in __constant__ (LDCU port).

#define DIM 32
#define THREADS 128
#define ROWS_PER_BLOCK 128

// staging for prep output: [0..1023] = upper-masked A^T, [1024..2047] = lower-masked
__device__   float  g_T[2 * DIM * DIM];
__constant__ float4 c_T4[2 * DIM * 8];   // col j: c_T4[j*8+q] (upper), c_T4[256+j*8+q] (lower)

__global__ void prep_kernel(const float* __restrict__ P)
{
    int e = threadIdx.x;                 // 1024 threads
    int j = e >> 5, k = e & 31;          // column j, row k
    float a = -P[k * DIM + j] / P[k * DIM + k];   // A[k][j]
    g_T[e]              = (k < j) ? a : 0.0f;     // strict upper (k<j)
    g_T[DIM * DIM + e]  = (k > j) ? a : 0.0f;     // strict lower (k>j)
}

__device__ __forceinline__ unsigned long long f2u(float2 v) {
    unsigned long long u; __builtin_memcpy(&u, &v, 8); return u;
}
__device__ __forceinline__ float2 u2f(unsigned long long u) {
    float2 v; __builtin_memcpy(&v, &u, 8); return v;
}
__device__ __forceinline__ float2 ffma2(float2 a, float2 b, float2 c) {
    unsigned long long d;
    asm("fma.rn.f32x2 %0, %1, %2, %3;"
        : "=l"(d) : "l"(f2u(a)), "l"(f2u(b)), "l"(f2u(c)));
    return u2f(d);
}

__global__ __launch_bounds__(THREADS, 8)
void gibbs_sweep_kernel(const float* __restrict__ x,
                        const float* __restrict__ noise,
                        const float* __restrict__ P,
                        const float* __restrict__ mu,
                        float* __restrict__ out,
                        int B)
{
    __shared__ float sgf[DIM];                 // sigma_i = sqrt(1/P_ii)
    __shared__ float muf[DIM];
    // One pad-33 scalar buffer (128 rows x 33), reused sequentially:
    //   (1) base stage -> read into r regs
    //   (2) x_old stage -> streamed scalars in phase 1
    //   (3) float4 swizzled out-stage (16KB fits inside)
    __shared__ __align__(16) float buf[ROWS_PER_BLOCK * 33];

    const int tid = threadIdx.x;

    if (tid < DIM) {
        float pii = P[tid * DIM + tid];
        sgf[tid] = sqrtf(1.0f / pii);
        muf[tid] = mu[tid];
    }
    __syncthreads();

    const int R0 = blockIdx.x * ROWS_PER_BLOCK;

    // ---- stage base = mu + sigma*noise into pad-33 (coalesced LDG, scalar STS) ----
    const float4* gn = (const float4*)noise;
    #pragma unroll
    for (int k = 0; k < 8; ++k) {
        int idx = k * THREADS + tid;           // 0..1023, coalesced
        int row = idx >> 3;
        int c   = idx & 7;
        int gr  = R0 + row;
        float4 n4 = (gr < B) ? gn[(size_t)gr * 8 + c]
                             : make_float4(0.f, 0.f, 0.f, 0.f);
        float* d = buf + row * 33 + c * 4;     // banks (row+4c+l)%32: conflict-free
        d[0] = fmaf(sgf[c * 4 + 0], n4.x, muf[c * 4 + 0]);
        d[1] = fmaf(sgf[c * 4 + 1], n4.y, muf[c * 4 + 1]);
        d[2] = fmaf(sgf[c * 4 + 2], n4.z, muf[c * 4 + 2]);
        d[3] = fmaf(sgf[c * 4 + 3], n4.w, muf[c * 4 + 3]);
    }
    __syncthreads();

    // ---- r <- base (scalar LDS, bank = (tid+j)%32 conflict-free) ----
    const float* myrow = buf + tid * 33;
    float2 r[16];
    #pragma unroll
    for (int j = 0; j < 16; ++j)
        r[j] = make_float2(myrow[2 * j], myrow[2 * j + 1]);
    __syncthreads();

    // ---- stage x_old into pad-33 (coalesced LDG.128, scalar STS) ----
    const float4* gx = (const float4*)x;
    #pragma unroll
    for (int k = 0; k < 8; ++k) {
        int idx = k * THREADS + tid;
        int row = idx >> 3;
        int c   = idx & 7;
        int gr  = R0 + row;
        float4 v = (gr < B) ? gx[(size_t)gr * 8 + c]
                            : make_float4(0.f, 0.f, 0.f, 0.f);
        float* d = buf + row * 33 + c * 4;
        d[0] = v.x; d[1] = v.y; d[2] = v.z; d[3] = v.w;
    }
    __syncthreads();

    // ---- Phase 1: r += U x_old, column order (x_old scalar from smem) ----
    #pragma unroll
    for (int j = 1; j < DIM; ++j) {
        float xj = myrow[j];                   // conflict-free scalar LDS
        float2 xs = make_float2(xj, xj);
        #pragma unroll
        for (int q = 0; q < (j + 3) >> 2; ++q) {
            float4 col = c_T4[j * 8 + q];      // masked: entries k>=j are 0
            r[2 * q]     = ffma2(xs, make_float2(col.x, col.y), r[2 * q]);
            r[2 * q + 1] = ffma2(xs, make_float2(col.z, col.w), r[2 * q + 1]);
        }
    }

    // ---- Phase 2: forward substitution, column order (no reductions) ----
    #pragma unroll
    for (int j = 0; j < DIM - 1; ++j) {
        float xj = (j & 1) ? r[j >> 1].y : r[j >> 1].x;   // r_j is final = x_j
        float2 xs = make_float2(xj, xj);
        #pragma unroll
        for (int q = j >> 2; q < 8; ++q) {
            float4 col = c_T4[256 + j * 8 + q]; // masked: entries k<=j are 0
            r[2 * q]     = ffma2(xs, make_float2(col.x, col.y), r[2 * q]);
            r[2 * q + 1] = ffma2(xs, make_float2(col.z, col.w), r[2 * q + 1]);
        }
    }

    __syncthreads();   // everyone done reading x_old before clobbering buf
    // ---- scatter rows to swizzled float4 stage, then coalesced STG.128 ----
    float4* st4 = (float4*)buf;
    const int sw = (tid >> 2) & 7;
    #pragma unroll
    for (int c = 0; c < 8; ++c) {
        st4[tid * 8 + (c ^ sw)] =
            make_float4(r[2 * c].x, r[2 * c].y, r[2 * c + 1].x, r[2 * c + 1].y);
    }
    __syncthreads();
    float4* gout = (float4*)out;
    #pragma unroll
    for (int k = 0; k < 8; ++k) {
        int idx = k * THREADS + tid;
        int row = idx >> 3;
        int c   = idx & 7;
        int gr  = R0 + row;
        if (gr < B) gout[(size_t)gr * 8 + c] = st4[row * 8 + (c ^ ((row >> 2) & 7))];
    }
}

extern "C" void kernel_launch(void* const* d_in, const int* in_sizes, int n_in,
                              void* d_out, int out_size)
{
    const float* x     = (const float*)d_in[0];
    const float* noise = (const float*)d_in[1];
    const float* P     = (const float*)d_in[2];
    const float* mu    = (const float*)d_in[3];
    float* out = (float*)d_out;

    int B = in_sizes[0] / DIM;

    // 1) build masked column tables on device
    prep_kernel<<<1, DIM * DIM>>>(P);

    // 2) D2D copy to __constant__ (graph-capturable memcpy node)
    void* gT_addr = nullptr;
    cudaGetSymbolAddress(&gT_addr, g_T);
    cudaMemcpyToSymbolAsync(c_T4, gT_addr, sizeof(float) * 2 * DIM * DIM, 0,
                            cudaMemcpyDeviceToDevice, 0);

    // 3) the sweep
    int grid = (B + ROWS_PER_BLOCK - 1) / ROWS_PER_BLOCK;
    gibbs_sweep_kernel<<<grid, THREADS>>>(x, noise, P, mu, out, B);
}